// round 1
// baseline (speedup 1.0000x reference)
#include <cuda_runtime.h>
#include <math.h>

#define DM    1024
#define BATCHN 1024
#define HEADS 16
#define DK    64

// Scratch (no allocations allowed)
__device__ float g_qkv[3u * BATCHN * DM];   // q | k | v, each [BATCH, DM] row-major, col = h*64+d
__device__ float g_beta[BATCHN * HEADS];
__device__ float g_outh[BATCHN * DM];

// ---------------------------------------------------------------------------
// Tiled fp32 GEMM: C = A[1024,1024] @ B[1024,1024] (+bias)
// BlockTile 128x64, BK=16, 256 threads, 8x4 per-thread microtile.
// blockIdx.x selects among 3 (B,C) pairs (16 x-tiles each) so QKV fuses into
// one 384-CTA launch.
// ---------------------------------------------------------------------------
#define BM 128
#define BN 64
#define BK 16
#define TM 8
#define TN 4

__global__ __launch_bounds__(256) void gemm3_kernel(
    const float* __restrict__ A,
    const float* __restrict__ B0, const float* __restrict__ B1, const float* __restrict__ B2,
    float* __restrict__ C0, float* __restrict__ C1, float* __restrict__ C2,
    const float* __restrict__ bias)
{
    __shared__ float As[BK][BM];
    __shared__ float Bs[BK][BN];

    const int tid = threadIdx.x;
    const int ty = tid >> 4;        // 0..15 -> row group of 8
    const int tx = tid & 15;        // 0..15 -> col group of 4

    const int sel     = blockIdx.x >> 4;             // 0..2
    const int colBase = (blockIdx.x & 15) * BN;
    const int rowBase = blockIdx.y * BM;

    const float* B = (sel == 0) ? B0 : (sel == 1) ? B1 : B2;
    float*       C = (sel == 0) ? C0 : (sel == 1) ? C1 : C2;

    float acc[TM][TN];
#pragma unroll
    for (int i = 0; i < TM; i++)
#pragma unroll
        for (int j = 0; j < TN; j++) acc[i][j] = 0.f;

    for (int kt = 0; kt < DM; kt += BK) {
        // A tile: 128x16 = 512 float4, 2 per thread, stored transposed As[k][m]
#pragma unroll
        for (int l = 0; l < 2; l++) {
            int id = tid + l * 256;        // 0..511
            int r  = id >> 2;              // 0..127
            int c4 = (id & 3) << 2;        // 0,4,8,12
            float4 va = *reinterpret_cast<const float4*>(
                &A[(size_t)(rowBase + r) * DM + kt + c4]);
            As[c4 + 0][r] = va.x;
            As[c4 + 1][r] = va.y;
            As[c4 + 2][r] = va.z;
            As[c4 + 3][r] = va.w;
        }
        // B tile: 16x64 = 256 float4, 1 per thread
        {
            int r  = tid >> 4;             // 0..15
            int c4 = (tid & 15) << 2;      // 0..60
            float4 vb = *reinterpret_cast<const float4*>(
                &B[(size_t)(kt + r) * DM + colBase + c4]);
            *reinterpret_cast<float4*>(&Bs[r][c4]) = vb;
        }
        __syncthreads();

#pragma unroll
        for (int k = 0; k < BK; k++) {
            float a[TM], bb[TN];
            float4 a0 = *reinterpret_cast<const float4*>(&As[k][ty * TM]);
            float4 a1 = *reinterpret_cast<const float4*>(&As[k][ty * TM + 4]);
            a[0] = a0.x; a[1] = a0.y; a[2] = a0.z; a[3] = a0.w;
            a[4] = a1.x; a[5] = a1.y; a[6] = a1.z; a[7] = a1.w;
            float4 b4 = *reinterpret_cast<const float4*>(&Bs[k][tx * TN]);
            bb[0] = b4.x; bb[1] = b4.y; bb[2] = b4.z; bb[3] = b4.w;
#pragma unroll
            for (int i = 0; i < TM; i++)
#pragma unroll
                for (int j = 0; j < TN; j++)
                    acc[i][j] = fmaf(a[i], bb[j], acc[i][j]);
        }
        __syncthreads();
    }

    float4 bv = make_float4(0.f, 0.f, 0.f, 0.f);
    if (bias) bv = *reinterpret_cast<const float4*>(&bias[colBase + tx * TN]);
#pragma unroll
    for (int i = 0; i < TM; i++) {
        int r = rowBase + ty * TM + i;
        float4 o;
        o.x = acc[i][0] + bv.x;
        o.y = acc[i][1] + bv.y;
        o.z = acc[i][2] + bv.z;
        o.w = acc[i][3] + bv.w;
        *reinterpret_cast<float4*>(&C[(size_t)r * DM + colBase + tx * TN]) = o;
    }
}

// ---------------------------------------------------------------------------
// beta = sigmoid(x @ Wg)  -> [BATCH, HEADS]
// one block per batch row; 16 warps, one per head
// ---------------------------------------------------------------------------
__global__ __launch_bounds__(512) void beta_kernel(
    const float* __restrict__ x, const float* __restrict__ Wg,
    float* __restrict__ beta)
{
    __shared__ float xs[DM];
    const int b = blockIdx.x;
    for (int i = threadIdx.x; i < DM; i += 512) xs[i] = x[(size_t)b * DM + i];
    __syncthreads();
    const int w    = threadIdx.x >> 5;   // head
    const int lane = threadIdx.x & 31;
    float s = 0.f;
    for (int j = lane; j < DM; j += 32) s = fmaf(xs[j], Wg[(size_t)j * HEADS + w], s);
#pragma unroll
    for (int off = 16; off; off >>= 1) s += __shfl_xor_sync(0xffffffffu, s, off);
    if (lane == 0) beta[b * HEADS + w] = 1.f / (1.f + expf(-s));
}

// ---------------------------------------------------------------------------
// Fast-weight delta-rule per (b,h):
//   v_ex = W k ;  dv = beta*(v - v_ex)
//   W'   = W + dv k^T           (written to d_out region)
//   o    = W' q = W q + dv (k.q)
// One 64-thread CTA per (b,h). W tile staged in padded shared.
// ---------------------------------------------------------------------------
__global__ __launch_bounds__(64) void fastweight_kernel(
    const float* __restrict__ weights,
    const float* __restrict__ q, const float* __restrict__ k,
    const float* __restrict__ v, const float* __restrict__ beta,
    float* __restrict__ nw, float* __restrict__ outh)
{
    __shared__ float Wsh[DK][DK + 1];
    __shared__ float ksh[DK], qsh[DK], dsh[DK];

    const int bh = blockIdx.x;
    const int b  = bh >> 4;
    const int h  = bh & 15;
    const int t  = threadIdx.x;

    // coalesced float4 load of the 64x64 tile
    const float4* W4 = reinterpret_cast<const float4*>(weights + (size_t)bh * (DK * DK));
#pragma unroll
    for (int i = 0; i < 16; i++) {
        int id = t + i * 64;               // 0..1023 float4s
        float4 wv = W4[id];
        int e = id << 2;
        int r = e >> 6, c = e & 63;
        Wsh[r][c + 0] = wv.x;
        Wsh[r][c + 1] = wv.y;
        Wsh[r][c + 2] = wv.z;
        Wsh[r][c + 3] = wv.w;
    }
    const size_t base = (size_t)b * DM + (size_t)h * DK;
    const float kval = k[base + t];
    const float qval = q[base + t];
    const float vval = v[base + t];
    ksh[t] = kval;
    qsh[t] = qval;
    const float betav = beta[bh];
    __syncthreads();

    // v_existing for row t (padded shared -> conflict-free)
    float s = 0.f;
#pragma unroll
    for (int j = 0; j < DK; j++) s = fmaf(Wsh[t][j], ksh[j], s);
    const float dv = betav * (vval - s);
    dsh[t] = dv;
    __syncthreads();

    // out row t: W[t,:].q + dv * (k.q)
    float s2 = 0.f, kq = 0.f;
#pragma unroll
    for (int j = 0; j < DK; j++) {
        s2 = fmaf(Wsh[t][j], qsh[j], s2);
        kq = fmaf(ksh[j], qsh[j], kq);
    }
    outh[base + t] = s2 + dv * kq;

    // new weights, coalesced: thread t owns column t
    float* NW = nw + (size_t)bh * (DK * DK);
#pragma unroll 8
    for (int vr = 0; vr < DK; vr++) {
        NW[vr * DK + t] = Wsh[vr][t] + dsh[vr] * kval;
    }
}

// ---------------------------------------------------------------------------
extern "C" void kernel_launch(void* const* d_in, const int* in_sizes, int n_in,
                              void* d_out, int out_size)
{
    const float* x       = (const float*)d_in[0];
    const float* weights = (const float*)d_in[1];
    const float* Wq      = (const float*)d_in[2];
    const float* Wk      = (const float*)d_in[3];
    const float* Wv      = (const float*)d_in[4];
    const float* Wg      = (const float*)d_in[5];
    const float* Wo      = (const float*)d_in[6];
    const float* bo      = (const float*)d_in[7];

    float* out = (float*)d_out;                       // [1024,1024]
    float* nw  = out + (size_t)BATCHN * DM;           // [1024,16,64,64]

    float *qb, *bb, *oh;
    cudaGetSymbolAddress((void**)&qb, g_qkv);
    cudaGetSymbolAddress((void**)&bb, g_beta);
    cudaGetSymbolAddress((void**)&oh, g_outh);
    float* kb = qb + (size_t)BATCHN * DM;
    float* vb = kb + (size_t)BATCHN * DM;

    // 1) fused Q/K/V projections: 3x (1024^3) GEMM in one 384-CTA launch
    gemm3_kernel<<<dim3(48, 8), 256>>>(x, Wq, Wk, Wv, qb, kb, vb, nullptr);
    // 2) gate
    beta_kernel<<<BATCHN, 512>>>(x, Wg, bb);
    // 3) fast-weight update + read (writes new_weights directly into d_out)
    fastweight_kernel<<<BATCHN * HEADS, 64>>>(weights, qb, kb, vb, bb, nw, oh);
    // 4) output projection + bias
    gemm3_kernel<<<dim3(16, 8), 256>>>(oh, Wo, Wo, Wo, out, out, out, bo);
}

// round 4
// speedup vs baseline: 1.4569x; 1.4569x over previous
#include <cuda_runtime.h>
#include <cuda_bf16.h>
#include <cstdint>
#include <math.h>

#define DM     1024
#define BATCHN 1024
#define HEADS  16
#define DK     64

// ---------------- scratch (no allocation allowed) ----------------
__device__ float g_qkv[3u * BATCHN * DM];            // q | k | v fp32
__device__ float g_beta[BATCHN * HEADS];
__device__ float g_outh[BATCHN * DM];                // per-head attention out fp32
__device__ __nv_bfloat16 g_xh[BATCHN * DM];          // x split hi
__device__ __nv_bfloat16 g_xl[BATCHN * DM];          // x split lo
__device__ __nv_bfloat16 g_wth[4u * DM * DM];        // W^T split hi: Wq,Wk,Wv,Wo
__device__ __nv_bfloat16 g_wtl[4u * DM * DM];        // W^T split lo
__device__ __nv_bfloat16 g_ohh[BATCHN * DM];         // outh split hi
__device__ __nv_bfloat16 g_ohl[BATCHN * DM];         // outh split lo

// ---------------------------------------------------------------------------
// split fp32 -> bf16 hi/lo
// ---------------------------------------------------------------------------
__global__ __launch_bounds__(256) void split_kernel(
    const float* __restrict__ in, __nv_bfloat16* __restrict__ hi,
    __nv_bfloat16* __restrict__ lo)
{
    int idx = blockIdx.x * 256 + threadIdx.x;   // float4 index
    float4 v = reinterpret_cast<const float4*>(in)[idx];
    float f[4] = {v.x, v.y, v.z, v.w};
    __nv_bfloat16 h[4], l[4];
#pragma unroll
    for (int i = 0; i < 4; i++) {
        h[i] = __float2bfloat16_rn(f[i]);
        l[i] = __float2bfloat16_rn(f[i] - __bfloat162float(h[i]));
    }
    __nv_bfloat162* h2 = reinterpret_cast<__nv_bfloat162*>(hi);
    __nv_bfloat162* l2 = reinterpret_cast<__nv_bfloat162*>(lo);
    h2[idx * 2 + 0] = __nv_bfloat162(h[0], h[1]);
    h2[idx * 2 + 1] = __nv_bfloat162(h[2], h[3]);
    l2[idx * 2 + 0] = __nv_bfloat162(l[0], l[1]);
    l2[idx * 2 + 1] = __nv_bfloat162(l[2], l[3]);
}

// ---------------------------------------------------------------------------
// transpose + split: W[K][N] -> Wt hi/lo [N][K] bf16. z selects matrix.
// ---------------------------------------------------------------------------
__global__ __launch_bounds__(256) void transsplit_kernel(
    const float* __restrict__ W0, const float* __restrict__ W1,
    const float* __restrict__ W2, const float* __restrict__ W3,
    __nv_bfloat16* __restrict__ hi, __nv_bfloat16* __restrict__ lo)
{
    __shared__ float tile[32][33];
    const int z = blockIdx.z;
    const float* W = (z == 0) ? W0 : (z == 1) ? W1 : (z == 2) ? W2 : W3;
    __nv_bfloat16* H = hi + (size_t)z * DM * DM;
    __nv_bfloat16* L = lo + (size_t)z * DM * DM;
    const int tx = threadIdx.x & 31, ty = threadIdx.x >> 5;
    const int nb = blockIdx.x * 32, kb = blockIdx.y * 32;
#pragma unroll
    for (int i = 0; i < 4; i++) {
        int k = kb + ty + i * 8;
        tile[ty + i * 8][tx] = W[(size_t)k * DM + nb + tx];
    }
    __syncthreads();
#pragma unroll
    for (int i = 0; i < 4; i++) {
        int n = nb + ty + i * 8;
        float v = tile[tx][ty + i * 8];
        __nv_bfloat16 h = __float2bfloat16_rn(v);
        __nv_bfloat16 l = __float2bfloat16_rn(v - __bfloat162float(h));
        H[(size_t)n * DM + kb + tx] = h;
        L[(size_t)n * DM + kb + tx] = l;
    }
}

// ---------------------------------------------------------------------------
// bf16-split GEMM on mma.sync (HMMA, base-target safe):
// C[M,N] = A @ B^T, A=(Ah,Al)[M,K] bf16 row-major, Bt=(Bth,Btl)[N,K] bf16.
// C = Ah*Bh + Al*Bh + Ah*Bl (fp32 accum). CTA tile 128x128, BK=32,
// 8 warps (2 x 4), warp tile 64x32, 2-stage cp.async pipeline.
// ---------------------------------------------------------------------------
#define TSTRIDE   80                    // bytes per 32-bf16 smem row (+16 pad)
#define TILE_B    (128 * TSTRIDE)       // 10240 per operand tile
#define MM_STAGE  (4 * TILE_B)          // Ah | Al | Bh | Bl
#define MM_SMEM   (2 * MM_STAGE)        // 81920

__device__ __forceinline__ void mma_bf16(float* c, const uint32_t* a, const uint32_t* b) {
    asm volatile(
        "mma.sync.aligned.m16n8k16.row.col.f32.bf16.bf16.f32 "
        "{%0,%1,%2,%3}, {%4,%5,%6,%7}, {%8,%9}, {%0,%1,%2,%3};"
        : "+f"(c[0]), "+f"(c[1]), "+f"(c[2]), "+f"(c[3])
        : "r"(a[0]), "r"(a[1]), "r"(a[2]), "r"(a[3]), "r"(b[0]), "r"(b[1]));
}

__device__ __forceinline__ void cp16(void* s, const void* g) {
    uint32_t sa;
    asm("{ .reg .u64 t; cvta.to.shared.u64 t, %1; cvt.u32.u64 %0, t; }" : "=r"(sa) : "l"(s));
    asm volatile("cp.async.cg.shared.global [%0], [%1], 16;" :: "r"(sa), "l"(g));
}

// load one 4-tile stage (Ah,Al,Bh,Bl), 8 x 16B per thread
__device__ __forceinline__ void cp_stage(
    char* smStage,
    const char* aH, const char* aL, const char* bH, const char* bL,
    int ktBytes, int tid)
{
    const char* srcs[4] = {aH, aL, bH, bL};
#pragma unroll
    for (int i = 0; i < 8; i++) {
        const int tile  = i >> 1;
        const int chunk = ((i & 1) << 8) + tid;     // 0..511
        const int r = chunk >> 2, c = chunk & 3;
        cp16(smStage + tile * TILE_B + r * TSTRIDE + c * 16,
             srcs[tile] + ((size_t)r << 11) + ktBytes + (c << 4));
    }
    asm volatile("cp.async.commit_group;");
}

__global__ __launch_bounds__(256, 2) void mm_kernel(
    const __nv_bfloat16* __restrict__ Ah, const __nv_bfloat16* __restrict__ Al,
    const __nv_bfloat16* __restrict__ Bth0, const __nv_bfloat16* __restrict__ Btl0,
    const __nv_bfloat16* __restrict__ Bth1, const __nv_bfloat16* __restrict__ Btl1,
    const __nv_bfloat16* __restrict__ Bth2, const __nv_bfloat16* __restrict__ Btl2,
    float* __restrict__ C0, float* __restrict__ C1, float* __restrict__ C2,
    const float* __restrict__ bias)
{
    extern __shared__ char sm[];
    const int tid = threadIdx.x;
    const int warp = tid >> 5, lane = tid & 31;
    const int g = lane >> 2, tg = lane & 3;
    const int z = blockIdx.z;
    const __nv_bfloat16* Bth = (z == 0) ? Bth0 : (z == 1) ? Bth1 : Bth2;
    const __nv_bfloat16* Btl = (z == 0) ? Btl0 : (z == 1) ? Btl1 : Btl2;
    float* C = (z == 0) ? C0 : (z == 1) ? C1 : C2;

    const int rowBase = blockIdx.y * 128;
    const int colBase = blockIdx.x * 128;
    const int warpRow = (warp & 1) * 64;       // 2 warp-rows of 64
    const int warpCol = (warp >> 1) * 32;      // 4 warp-cols of 32

    // source bases pre-offset by CTA tile position (bytes; row stride 2048)
    const char* aHp = (const char*)Ah  + ((size_t)rowBase << 11);
    const char* aLp = (const char*)Al  + ((size_t)rowBase << 11);
    const char* bHp = (const char*)Bth + ((size_t)colBase << 11);
    const char* bLp = (const char*)Btl + ((size_t)colBase << 11);

    float acc[4][4][4];
#pragma unroll
    for (int mi = 0; mi < 4; mi++)
#pragma unroll
        for (int ni = 0; ni < 4; ni++)
#pragma unroll
            for (int e = 0; e < 4; e++) acc[mi][ni][e] = 0.f;

    // prologue: 2 stages in flight
    cp_stage(sm,            aHp, aLp, bHp, bLp, 0,  tid);
    cp_stage(sm + MM_STAGE, aHp, aLp, bHp, bLp, 64, tid);

    for (int it = 0; it < 32; it++) {
        if (it == 31) asm volatile("cp.async.wait_group 0;" ::: "memory");
        else          asm volatile("cp.async.wait_group 1;" ::: "memory");
        __syncthreads();

        char* so = sm + (it & 1) * MM_STAGE;
#pragma unroll
        for (int ks = 0; ks < 2; ks++) {
            const int kb = ks * 32 + tg * 4;   // byte offset within row
            // A-hi fragments (64 rows)
            uint32_t ahf[4][4];
#pragma unroll
            for (int mi = 0; mi < 4; mi++) {
                const char* p = so + (warpRow + mi * 16 + g) * TSTRIDE + kb;
                ahf[mi][0] = *(const uint32_t*)(p);
                ahf[mi][1] = *(const uint32_t*)(p + 8 * TSTRIDE);
                ahf[mi][2] = *(const uint32_t*)(p + 16);
                ahf[mi][3] = *(const uint32_t*)(p + 8 * TSTRIDE + 16);
            }
            // B-hi fragments (32 cols)
            uint32_t bhf[4][2];
#pragma unroll
            for (int ni = 0; ni < 4; ni++) {
                const char* p = so + 2 * TILE_B + (warpCol + ni * 8 + g) * TSTRIDE + kb;
                bhf[ni][0] = *(const uint32_t*)(p);
                bhf[ni][1] = *(const uint32_t*)(p + 16);
            }
            // pass 1: Ah * Bh
#pragma unroll
            for (int mi = 0; mi < 4; mi++)
#pragma unroll
                for (int ni = 0; ni < 4; ni++)
                    mma_bf16(acc[mi][ni], ahf[mi], bhf[ni]);
            // pass 2: Al * Bh
            {
                uint32_t alf[4][4];
#pragma unroll
                for (int mi = 0; mi < 4; mi++) {
                    const char* p = so + TILE_B + (warpRow + mi * 16 + g) * TSTRIDE + kb;
                    alf[mi][0] = *(const uint32_t*)(p);
                    alf[mi][1] = *(const uint32_t*)(p + 8 * TSTRIDE);
                    alf[mi][2] = *(const uint32_t*)(p + 16);
                    alf[mi][3] = *(const uint32_t*)(p + 8 * TSTRIDE + 16);
                }
#pragma unroll
                for (int mi = 0; mi < 4; mi++)
#pragma unroll
                    for (int ni = 0; ni < 4; ni++)
                        mma_bf16(acc[mi][ni], alf[mi], bhf[ni]);
            }
            // pass 3: Ah * Bl
            {
                uint32_t blf[4][2];
#pragma unroll
                for (int ni = 0; ni < 4; ni++) {
                    const char* p = so + 3 * TILE_B + (warpCol + ni * 8 + g) * TSTRIDE + kb;
                    blf[ni][0] = *(const uint32_t*)(p);
                    blf[ni][1] = *(const uint32_t*)(p + 16);
                }
#pragma unroll
                for (int mi = 0; mi < 4; mi++)
#pragma unroll
                    for (int ni = 0; ni < 4; ni++)
                        mma_bf16(acc[mi][ni], ahf[mi], blf[ni]);
            }
        }
        __syncthreads();
        if (it + 2 < 32)
            cp_stage(so, aHp, aLp, bHp, bLp, (it + 2) * 64, tid);
    }

    // epilogue: direct float2 stores
#pragma unroll
    for (int mi = 0; mi < 4; mi++) {
        const int row0 = rowBase + warpRow + mi * 16 + g;
#pragma unroll
        for (int ni = 0; ni < 4; ni++) {
            const int col = colBase + warpCol + ni * 8 + tg * 2;
            float b0 = 0.f, b1 = 0.f;
            if (bias) { b0 = bias[col]; b1 = bias[col + 1]; }
            float2 v0 = make_float2(acc[mi][ni][0] + b0, acc[mi][ni][1] + b1);
            float2 v1 = make_float2(acc[mi][ni][2] + b0, acc[mi][ni][3] + b1);
            *reinterpret_cast<float2*>(&C[(size_t)row0 * DM + col]) = v0;
            *reinterpret_cast<float2*>(&C[(size_t)(row0 + 8) * DM + col]) = v1;
        }
    }
}

// ---------------------------------------------------------------------------
// beta = sigmoid(x @ Wg)
// ---------------------------------------------------------------------------
__global__ __launch_bounds__(512) void beta_kernel(
    const float* __restrict__ x, const float* __restrict__ Wg,
    float* __restrict__ beta)
{
    __shared__ float xs[DM];
    const int b = blockIdx.x;
    for (int i = threadIdx.x; i < DM; i += 512) xs[i] = x[(size_t)b * DM + i];
    __syncthreads();
    const int w = threadIdx.x >> 5, lane = threadIdx.x & 31;
    float s = 0.f;
    for (int j = lane; j < DM; j += 32) s = fmaf(xs[j], Wg[(size_t)j * HEADS + w], s);
#pragma unroll
    for (int off = 16; off; off >>= 1) s += __shfl_xor_sync(0xffffffffu, s, off);
    if (lane == 0) beta[b * HEADS + w] = 1.f / (1.f + expf(-s));
}

// ---------------------------------------------------------------------------
// fast-weight delta rule, one 64-thread CTA per (b,h)
// ---------------------------------------------------------------------------
__global__ __launch_bounds__(64) void fastweight_kernel(
    const float* __restrict__ weights,
    const float* __restrict__ q, const float* __restrict__ k,
    const float* __restrict__ v, const float* __restrict__ beta,
    float* __restrict__ nw, float* __restrict__ outh)
{
    __shared__ float Wsh[DK][DK + 1];
    __shared__ float ksh[DK], qsh[DK], dsh[DK];

    const int bh = blockIdx.x;
    const int b = bh >> 4, h = bh & 15;
    const int t = threadIdx.x;

    const float4* W4 = reinterpret_cast<const float4*>(weights + (size_t)bh * (DK * DK));
#pragma unroll
    for (int i = 0; i < 16; i++) {
        int id = t + i * 64;
        float4 wv = W4[id];
        int e = id << 2;
        int r = e >> 6, c = e & 63;
        Wsh[r][c + 0] = wv.x; Wsh[r][c + 1] = wv.y;
        Wsh[r][c + 2] = wv.z; Wsh[r][c + 3] = wv.w;
    }
    const size_t base = (size_t)b * DM + (size_t)h * DK;
    const float kval = k[base + t];
    const float qval = q[base + t];
    const float vval = v[base + t];
    ksh[t] = kval; qsh[t] = qval;
    const float betav = beta[bh];
    __syncthreads();

    float s = 0.f;
#pragma unroll
    for (int j = 0; j < DK; j++) s = fmaf(Wsh[t][j], ksh[j], s);
    const float dv = betav * (vval - s);
    dsh[t] = dv;
    __syncthreads();

    float s2 = 0.f, kq = 0.f;
#pragma unroll
    for (int j = 0; j < DK; j++) {
        s2 = fmaf(Wsh[t][j], qsh[j], s2);
        kq = fmaf(ksh[j], qsh[j], kq);
    }
    outh[base + t] = s2 + dv * kq;

    float* NW = nw + (size_t)bh * (DK * DK);
    const int r0 = t >> 4, c4 = (t & 15) << 2;
    float4 k4;
    k4.x = ksh[c4 + 0]; k4.y = ksh[c4 + 1]; k4.z = ksh[c4 + 2]; k4.w = ksh[c4 + 3];
#pragma unroll
    for (int vr = 0; vr < DK; vr += 4) {
        const int row = vr + r0;
        const float d = dsh[row];
        float4 o;
        o.x = Wsh[row][c4 + 0] + d * k4.x;
        o.y = Wsh[row][c4 + 1] + d * k4.y;
        o.z = Wsh[row][c4 + 2] + d * k4.z;
        o.w = Wsh[row][c4 + 3] + d * k4.w;
        *reinterpret_cast<float4*>(&NW[row * DK + c4]) = o;
    }
}

// ---------------------------------------------------------------------------
extern "C" void kernel_launch(void* const* d_in, const int* in_sizes, int n_in,
                              void* d_out, int out_size)
{
    const float* x       = (const float*)d_in[0];
    const float* weights = (const float*)d_in[1];
    const float* Wq      = (const float*)d_in[2];
    const float* Wk      = (const float*)d_in[3];
    const float* Wv      = (const float*)d_in[4];
    const float* Wg      = (const float*)d_in[5];
    const float* Wo      = (const float*)d_in[6];
    const float* bo      = (const float*)d_in[7];

    float* out = (float*)d_out;
    float* nw  = out + (size_t)BATCHN * DM;

    float *qb, *bb, *oh;
    __nv_bfloat16 *xh, *xl, *wth, *wtl, *ohh, *ohl;
    cudaGetSymbolAddress((void**)&qb,  g_qkv);
    cudaGetSymbolAddress((void**)&bb,  g_beta);
    cudaGetSymbolAddress((void**)&oh,  g_outh);
    cudaGetSymbolAddress((void**)&xh,  g_xh);
    cudaGetSymbolAddress((void**)&xl,  g_xl);
    cudaGetSymbolAddress((void**)&wth, g_wth);
    cudaGetSymbolAddress((void**)&wtl, g_wtl);
    cudaGetSymbolAddress((void**)&ohh, g_ohh);
    cudaGetSymbolAddress((void**)&ohl, g_ohl);
    float* kb = qb + (size_t)BATCHN * DM;
    float* vb = kb + (size_t)BATCHN * DM;

    cudaFuncSetAttribute(mm_kernel, cudaFuncAttributeMaxDynamicSharedMemorySize, MM_SMEM);

    const size_t MS = (size_t)DM * DM;

    // 1) transpose + bf16-split the four big weight matrices
    transsplit_kernel<<<dim3(32, 32, 4), 256>>>(Wq, Wk, Wv, Wo, wth, wtl);
    // 2) split x
    split_kernel<<<1024, 256>>>(x, xh, xl);
    // 3) gate
    beta_kernel<<<BATCHN, 512>>>(x, Wg, bb);
    // 4) QKV projections (fused, grid.z = 3)
    mm_kernel<<<dim3(8, 8, 3), 256, MM_SMEM>>>(
        xh, xl,
        wth + 0 * MS, wtl + 0 * MS,
        wth + 1 * MS, wtl + 1 * MS,
        wth + 2 * MS, wtl + 2 * MS,
        qb, kb, vb, nullptr);
    // 5) fast-weight update + read
    fastweight_kernel<<<BATCHN * HEADS, 64>>>(weights, qb, kb, vb, bb, nw, oh);
    // 6) split outh
    split_kernel<<<1024, 256>>>(oh, ohh, ohl);
    // 7) output projection + bias
    mm_kernel<<<dim3(8, 8, 1), 256, MM_SMEM>>>(
        ohh, ohl,
        wth + 3 * MS, wtl + 3 * MS,
        wth + 3 * MS, wtl + 3 * MS,
        wth + 3 * MS, wtl + 3 * MS,
        out, out, out, bo);
}